// round 7
// baseline (speedup 1.0000x reference)
#include <cuda_runtime.h>
#include <cuda_bf16.h>

// PointLayerNorm, R7: single persistent kernel, 8 segment-aligned chunks.
// Per chunk: cooperative reduce (x pulled into L2, default policy) ->
// software grid barrier -> per-block stats -> norm (x re-read from L2 with
// __ldcs evict-first, out stored __stcs). DRAM traffic 921 -> ~614 MB.

#define Bc 4
#define Nc 200000
#define Cc 96
#define C4 (Cc / 4)          // 24 float4 per point
#define Sc 32
#define KEYS (Bc * Sc)
#define EPSF 1e-5f
#define SPC 4                // segments per chunk
#define NCHUNKS (Sc / SPC)   // 8
#define GRID 576             // co-resident (<= 4 blocks/SM * 148 SMs)
#define TPB 256

__device__ float g_sum[KEYS];
__device__ float g_sumsq[KEYS];
__device__ unsigned g_bar_count;          // zero-init; returns to 0 each barrier
__device__ volatile unsigned g_bar_phase; // monotonically increases

__global__ void pln_zero_kernel() {
    int i = threadIdx.x;
    if (i < KEYS) { g_sum[i] = 0.f; g_sumsq[i] = 0.f; }
}

__device__ __forceinline__ void grid_barrier(unsigned& lp) {
    __syncthreads();
    if (threadIdx.x == 0) {
        __threadfence();
        unsigned t = atomicAdd(&g_bar_count, 1u);
        if (t == GRID - 1) {
            g_bar_count = 0;
            __threadfence();
            atomicAdd((unsigned*)&g_bar_phase, 1u);   // release
        } else {
            while (g_bar_phase == lp) { __nanosleep(64); }
        }
    }
    ++lp;
    __syncthreads();
    __threadfence();
}

__device__ __forceinline__ void flush_key(int key, float& sA, float& sB,
                                          float& s2A, float& s2B, int lane) {
    float s = sA + sB, s2 = s2A + s2B;
    #pragma unroll
    for (int o = 16; o; o >>= 1) {
        s  += __shfl_xor_sync(0xffffffffu, s,  o);
        s2 += __shfl_xor_sync(0xffffffffu, s2, o);
    }
    if (lane == 0) {
        atomicAdd(&g_sum[key],   s);
        atomicAdd(&g_sumsq[key], s2);
    }
    sA = sB = s2A = s2B = 0.f;
}

__global__ __launch_bounds__(TPB, 4) void pln_fused_kernel(
    const float4* __restrict__ x4, const int* __restrict__ idx,
    const int* __restrict__ offs,
    const float4* __restrict__ w4, const float4* __restrict__ b4,
    float4* __restrict__ out4)
{
    __shared__ float2 s_mi[Bc * SPC];   // [(b<<2)|ds] -> (mean, inv_std)

    const int tid    = blockIdx.x * blockDim.x + threadIdx.x;
    const int lane   = threadIdx.x & 31;
    const int wid    = tid >> 5;
    const int totalW = (GRID * TPB) >> 5;
    const int T      = GRID * TPB;        // 147456, multiple of 24
    const int dp     = T / C4;            // 6144
    const int c4     = tid % C4;
    const int nb     = tid / C4;

    unsigned lp = g_bar_phase;            // stable: no increments before barrier 1
    float4 wv = __ldg(w4 + c4);
    float4 bv = __ldg(b4 + c4);

    for (int c = 0; c < NCHUNKS; ++c) {
        const int s0  = c * SPC;
        const int n0  = __ldg(&offs[s0]);
        const int n1  = __ldg(&offs[s0 + SPC]);
        const int pts = n1 - n0;
        const int Q   = Bc * pts;

        // ---- reduce phase: warp-contiguous chunks over q in [0, Q) ----
        {
            int wchunk = (((Q + totalW - 1) / totalW) + 7) & ~7;
            int q0 = wid * wchunk;
            int q1 = min(q0 + wchunk, Q);
            if (q0 < q1) {
                int b = q0 / pts;
                int n = n0 + (q0 - b * pts);
                float sA = 0.f, sB = 0.f, s2A = 0.f, s2B = 0.f;
                int curKey = -1;
                int q = q0;
                while (q < q1) {
                    bool full = (q + 8 <= q1) && (n + 8 <= n1);
                    if (full) {
                        int kl = 0;
                        if (lane < 8) kl = (b * Sc + __ldg(&idx[n + lane])) & (KEYS - 1);
                        int k0 = __shfl_sync(0xffffffffu, kl, 0);
                        bool uni = __all_sync(0xffffffffu, lane >= 8 || kl == k0);
                        if (uni) {
                            if (k0 != curKey) {
                                if (curKey >= 0) flush_key(curKey, sA, sB, s2A, s2B, lane);
                                curKey = k0;
                            }
                            const float4* base = x4 + (size_t)(b * Nc + n) * C4;
                            float4 v0 = __ldg(base + lane);
                            float4 v1 = __ldg(base + lane + 32);
                            float4 v2 = __ldg(base + lane + 64);
                            float4 v3 = __ldg(base + lane + 96);
                            float4 v4 = __ldg(base + lane + 128);
                            float4 v5 = __ldg(base + lane + 160);
                            sA += (v0.x + v0.y) + (v0.z + v0.w) + (v2.x + v2.y)
                                + (v2.z + v2.w) + (v4.x + v4.y) + (v4.z + v4.w);
                            sB += (v1.x + v1.y) + (v1.z + v1.w) + (v3.x + v3.y)
                                + (v3.z + v3.w) + (v5.x + v5.y) + (v5.z + v5.w);
                            s2A = fmaf(v0.x, v0.x, s2A); s2A = fmaf(v0.y, v0.y, s2A);
                            s2A = fmaf(v0.z, v0.z, s2A); s2A = fmaf(v0.w, v0.w, s2A);
                            s2B = fmaf(v1.x, v1.x, s2B); s2B = fmaf(v1.y, v1.y, s2B);
                            s2B = fmaf(v1.z, v1.z, s2B); s2B = fmaf(v1.w, v1.w, s2B);
                            s2A = fmaf(v2.x, v2.x, s2A); s2A = fmaf(v2.y, v2.y, s2A);
                            s2A = fmaf(v2.z, v2.z, s2A); s2A = fmaf(v2.w, v2.w, s2A);
                            s2B = fmaf(v3.x, v3.x, s2B); s2B = fmaf(v3.y, v3.y, s2B);
                            s2B = fmaf(v3.z, v3.z, s2B); s2B = fmaf(v3.w, v3.w, s2B);
                            s2A = fmaf(v4.x, v4.x, s2A); s2A = fmaf(v4.y, v4.y, s2A);
                            s2A = fmaf(v4.z, v4.z, s2A); s2A = fmaf(v4.w, v4.w, s2A);
                            s2B = fmaf(v5.x, v5.x, s2B); s2B = fmaf(v5.y, v5.y, s2B);
                            s2B = fmaf(v5.z, v5.z, s2B); s2B = fmaf(v5.w, v5.w, s2B);
                            q += 8; n += 8;
                            if (n >= n1) { n = n0; ++b; }
                            continue;
                        }
                    }
                    { // slow path: one point (segment/batch boundary)
                        int key = (b * Sc + __ldg(&idx[n])) & (KEYS - 1);
                        if (key != curKey) {
                            if (curKey >= 0) flush_key(curKey, sA, sB, s2A, s2B, lane);
                            curKey = key;
                        }
                        if (lane < C4) {
                            float4 v = __ldg(x4 + (size_t)(b * Nc + n) * C4 + lane);
                            sA += (v.x + v.y) + (v.z + v.w);
                            s2A = fmaf(v.x, v.x, s2A); s2A = fmaf(v.y, v.y, s2A);
                            s2A = fmaf(v.z, v.z, s2A); s2A = fmaf(v.w, v.w, s2A);
                        }
                        ++q; ++n;
                        if (n >= n1) { n = n0; ++b; }
                    }
                }
                if (curKey >= 0) flush_key(curKey, sA, sB, s2A, s2B, lane);
            }
        }

        grid_barrier(lp);

        // ---- stats: 16 (mean, inv) pairs; __ldcg bypasses stale L1 ----
        if (threadIdx.x < Bc * SPC) {
            int kl = threadIdx.x;
            int bb = kl >> 2, ds = kl & (SPC - 1);
            int seg = s0 + ds;
            float cnt = (float)(__ldg(&offs[seg + 1]) - __ldg(&offs[seg])) * (float)Cc;
            int key = bb * Sc + seg;
            float m   = __ldcg(&g_sum[key])   / cnt;
            float var = __ldcg(&g_sumsq[key]) / cnt - m * m;
            s_mi[kl] = make_float2(m, rsqrtf(var + EPSF));
        }
        __syncthreads();

        // ---- norm phase: x from L2 (evict-first), out streamed ----
        {
            const int J = pts * C4;
            #pragma unroll
            for (int bb = 0; bb < Bc; ++bb) {
                size_t ebase = ((size_t)bb * Nc + n0) * C4;
                int n = n0 + nb;
                for (int j = tid; j < J; j += T) {
                    int ds = (__ldg(&idx[n]) - s0) & (SPC - 1);
                    float2 mi = s_mi[(bb << 2) | ds];
                    float4 xv = __ldcs(x4 + ebase + j);
                    float4 o; float sc, sh;
                    sc = mi.y * wv.x; sh = fmaf(-mi.x, sc, bv.x); o.x = fmaf(xv.x, sc, sh);
                    sc = mi.y * wv.y; sh = fmaf(-mi.x, sc, bv.y); o.y = fmaf(xv.y, sc, sh);
                    sc = mi.y * wv.z; sh = fmaf(-mi.x, sc, bv.z); o.z = fmaf(xv.z, sc, sh);
                    sc = mi.y * wv.w; sh = fmaf(-mi.x, sc, bv.w); o.w = fmaf(xv.w, sc, sh);
                    __stcs(out4 + ebase + j, o);
                    n += dp;
                }
            }
        }
        // no trailing barrier: next chunk's reduce touches disjoint keys;
        // the next grid_barrier re-aligns all blocks.
    }
}

extern "C" void kernel_launch(void* const* d_in, const int* in_sizes, int n_in,
                              void* d_out, int out_size) {
    const float4* x4   = (const float4*)d_in[0];
    const int*    offs = (const int*)d_in[1];
    const int*    idx  = (const int*)d_in[2];
    const float4* w4   = (const float4*)d_in[3];
    const float4* b4   = (const float4*)d_in[4];
    float4* out4 = (float4*)d_out;

    pln_zero_kernel<<<1, 128>>>();
    pln_fused_kernel<<<GRID, TPB>>>(x4, idx, offs, w4, b4, out4);
}

// round 8
// speedup vs baseline: 1.0920x; 1.0920x over previous
#include <cuda_runtime.h>
#include <cuda_bf16.h>

// PointLayerNorm, R8: R6 structure; reduce rewritten to exploit that
// batch_indices is NON-DECREASING (repeat(arange(S), diff)). Segment runs are
// derived from the 33-entry offs array, so the reduce inner loop is a pure
// 6x LDG.128 + FMA stream: no idx loads, no shuffles, no key checks.

#define Bc 4
#define Nc 200000
#define Cc 96
#define C4 (Cc / 4)            // 24 float4 per point
#define Sc 32
#define KEYS (Bc * Sc)
#define EPSF 1e-5f

__device__ float g_sum[KEYS];
__device__ float g_sumsq[KEYS];
__device__ float4 g_sc[KEYS * C4];   // per (key, c4) scale
__device__ float4 g_sh[KEYS * C4];   // per (key, c4) shift

__global__ void pln_zero_kernel() {
    int i = threadIdx.x;
    if (i < KEYS) { g_sum[i] = 0.f; g_sumsq[i] = 0.f; }
}

// Reduce: one warp owns a contiguous range of global points [g0, g1).
// Decompose into (batch, segment-run) pieces using offs only; accumulate each
// run with 8-point groups (6 LDG.128/lane, dual FMA chains), flush per run.
__global__ __launch_bounds__(256) void pln_reduce_kernel(
    const float4* __restrict__ x4, const int* __restrict__ offs)
{
    const int P = Bc * Nc;
    int wid    = (blockIdx.x * blockDim.x + threadIdx.x) >> 5;
    int lane   = threadIdx.x & 31;
    int totalW = (gridDim.x * blockDim.x) >> 5;
    int chunk  = (P + totalW - 1) / totalW;
    int g0 = wid * chunk;
    int g1 = min(g0 + chunk, P);
    if (g0 >= g1) return;

    int g = g0;
    while (g < g1) {
        int b = g / Nc;
        int n = g - b * Nc;
        int nlimit = min(Nc, n + (g1 - g));    // batch-local end of our range

        // locate segment containing n (<=32 L1-hit loads, once per batch-slice)
        int seg = 0;
        while (__ldg(&offs[seg + 1]) <= n) ++seg;

        while (n < nlimit) {
            int rend = min(nlimit, __ldg(&offs[seg + 1]));
            int key  = b * Sc + seg;

            float sA = 0.f, sB = 0.f, s2A = 0.f, s2B = 0.f;
            const float4* base = x4 + ((size_t)b * Nc + n) * C4;

            // 8-point groups: 192 consecutive float4s, 6 per lane.
            for (; n + 8 <= rend; n += 8, base += 192) {
                float4 v0 = __ldg(base + lane);
                float4 v1 = __ldg(base + lane + 32);
                float4 v2 = __ldg(base + lane + 64);
                float4 v3 = __ldg(base + lane + 96);
                float4 v4 = __ldg(base + lane + 128);
                float4 v5 = __ldg(base + lane + 160);
                sA += (v0.x + v0.y) + (v0.z + v0.w) + (v2.x + v2.y)
                    + (v2.z + v2.w) + (v4.x + v4.y) + (v4.z + v4.w);
                sB += (v1.x + v1.y) + (v1.z + v1.w) + (v3.x + v3.y)
                    + (v3.z + v3.w) + (v5.x + v5.y) + (v5.z + v5.w);
                s2A = fmaf(v0.x, v0.x, s2A); s2A = fmaf(v0.y, v0.y, s2A);
                s2A = fmaf(v0.z, v0.z, s2A); s2A = fmaf(v0.w, v0.w, s2A);
                s2B = fmaf(v1.x, v1.x, s2B); s2B = fmaf(v1.y, v1.y, s2B);
                s2B = fmaf(v1.z, v1.z, s2B); s2B = fmaf(v1.w, v1.w, s2B);
                s2A = fmaf(v2.x, v2.x, s2A); s2A = fmaf(v2.y, v2.y, s2A);
                s2A = fmaf(v2.z, v2.z, s2A); s2A = fmaf(v2.w, v2.w, s2A);
                s2B = fmaf(v3.x, v3.x, s2B); s2B = fmaf(v3.y, v3.y, s2B);
                s2B = fmaf(v3.z, v3.z, s2B); s2B = fmaf(v3.w, v3.w, s2B);
                s2A = fmaf(v4.x, v4.x, s2A); s2A = fmaf(v4.y, v4.y, s2A);
                s2A = fmaf(v4.z, v4.z, s2A); s2A = fmaf(v4.w, v4.w, s2A);
                s2B = fmaf(v5.x, v5.x, s2B); s2B = fmaf(v5.y, v5.y, s2B);
                s2B = fmaf(v5.z, v5.z, s2B); s2B = fmaf(v5.w, v5.w, s2B);
            }
            // remainder: single points, 24 active lanes
            for (; n < rend; ++n, base += 24) {
                if (lane < C4) {
                    float4 v = __ldg(base + lane);
                    sA += (v.x + v.y) + (v.z + v.w);
                    s2A = fmaf(v.x, v.x, s2A); s2A = fmaf(v.y, v.y, s2A);
                    s2A = fmaf(v.z, v.z, s2A); s2A = fmaf(v.w, v.w, s2A);
                }
            }

            // flush this run
            float s = sA + sB, s2 = s2A + s2B;
            #pragma unroll
            for (int o = 16; o; o >>= 1) {
                s  += __shfl_xor_sync(0xffffffffu, s,  o);
                s2 += __shfl_xor_sync(0xffffffffu, s2, o);
            }
            if (lane == 0) {
                atomicAdd(&g_sum[key],   s);
                atomicAdd(&g_sumsq[key], s2);
            }
            if (n < nlimit) ++seg;   // advance to next segment in this batch
        }
        g = b * Nc + nlimit;
        // next batch-slice starts at n=0 -> seg restarts from 0 (loop handles)
    }
}

// Per-(key, c4) scale/shift tables: o = x * sc + sh.
__global__ void pln_finalize_kernel(const int* __restrict__ offs,
                                    const float4* __restrict__ w4,
                                    const float4* __restrict__ b4)
{
    int i = blockIdx.x * blockDim.x + threadIdx.x;
    if (i < KEYS * C4) {
        int k  = i / C4;
        int c4 = i - k * C4;
        int seg = k & (Sc - 1);
        float cnt = (float)(offs[seg + 1] - offs[seg]) * (float)Cc;
        float m   = g_sum[k] / cnt;
        float var = g_sumsq[k] / cnt - m * m;
        float iv  = rsqrtf(var + EPSF);
        float4 wv = __ldg(w4 + c4);
        float4 bv = __ldg(b4 + c4);
        float4 sc, sh;
        sc.x = iv * wv.x; sh.x = fmaf(-m, sc.x, bv.x);
        sc.y = iv * wv.y; sh.y = fmaf(-m, sc.y, bv.y);
        sc.z = iv * wv.z; sh.z = fmaf(-m, sc.z, bv.z);
        sc.w = iv * wv.w; sh.w = fmaf(-m, sc.w, bv.w);
        g_sc[i] = sc;
        g_sh[i] = sh;
    }
}

// Norm: division-free, c4 loop-invariant per thread; already at the chip
// LTS cap (~6.4 TB/s combined) per R6 profile.
__global__ __launch_bounds__(256) void pln_norm_kernel(
    const float4* __restrict__ x4, const int* __restrict__ idx,
    float4* __restrict__ out4)
{
    const int P = Bc * Nc;
    const int E = P * C4;                      // 19,200,000 float4s
    int T   = gridDim.x * blockDim.x;          // multiple of 24 by launch config
    int tid = blockIdx.x * blockDim.x + threadIdx.x;
    int dp  = T / C4;

    int p  = tid / C4;
    int c4 = tid - p * C4;
    int b  = p / Nc;
    int n  = p - b * Nc;

    for (int e = tid; e < E; e += T) {
        int key = (b * Sc + __ldg(&idx[n])) & (KEYS - 1);
        int t   = key * C4 + c4;
        float4 sc = g_sc[t];
        float4 sh = g_sh[t];
        float4 xv = __ldcs(x4 + e);
        float4 o;
        o.x = fmaf(xv.x, sc.x, sh.x);
        o.y = fmaf(xv.y, sc.y, sh.y);
        o.z = fmaf(xv.z, sc.z, sh.z);
        o.w = fmaf(xv.w, sc.w, sh.w);
        __stcs(out4 + e, o);
        n += dp;
        if (n >= Nc) { n -= Nc; ++b; }
    }
}

extern "C" void kernel_launch(void* const* d_in, const int* in_sizes, int n_in,
                              void* d_out, int out_size) {
    const float4* x4   = (const float4*)d_in[0];
    const int*    offs = (const int*)d_in[1];
    const int*    idx  = (const int*)d_in[2];
    const float4* w4   = (const float4*)d_in[3];
    const float4* b4   = (const float4*)d_in[4];
    float4* out4 = (float4*)d_out;

    pln_zero_kernel<<<1, 128>>>();
    pln_reduce_kernel<<<2048, 256>>>(x4, offs);
    pln_finalize_kernel<<<12, 256>>>(offs, w4, b4);
    // grid*256 divisible by 24 -> grid divisible by 3.
    pln_norm_kernel<<<1185, 256>>>(x4, idx, out4);
}

// round 9
// speedup vs baseline: 1.2122x; 1.1101x over previous
#include <cuda_runtime.h>
#include <cuda_bf16.h>

// PointLayerNorm, R9: run-based reduce (no idx loads; segment runs from the
// 33-entry offs array) with persistent one-wave grid (592 blocks) and binary
// search for the starting segment. Norm kernel identical to R6 (LTS-cap).

#define Bc 4
#define Nc 200000
#define Cc 96
#define C4 (Cc / 4)            // 24 float4 per point
#define Sc 32
#define KEYS (Bc * Sc)
#define EPSF 1e-5f
#define RGRID 592              // 148 SMs x 4 blocks: exactly one wave

__device__ float g_sum[KEYS];
__device__ float g_sumsq[KEYS];
__device__ float4 g_sc[KEYS * C4];   // per (key, c4) scale
__device__ float4 g_sh[KEYS * C4];   // per (key, c4) shift

__global__ void pln_zero_kernel() {
    int i = threadIdx.x;
    if (i < KEYS) { g_sum[i] = 0.f; g_sumsq[i] = 0.f; }
}

// Reduce: one warp owns a contiguous range of global points [g0, g1).
// Decompose into (batch, segment-run) pieces using offs only; accumulate each
// run with 8-point groups (6 LDG.128/lane, dual FMA chains), flush per run.
__global__ __launch_bounds__(256) void pln_reduce_kernel(
    const float4* __restrict__ x4, const int* __restrict__ offs)
{
    const int P = Bc * Nc;
    int wid    = (blockIdx.x * blockDim.x + threadIdx.x) >> 5;
    int lane   = threadIdx.x & 31;
    int totalW = (RGRID * 256) >> 5;            // 4736 warps
    int chunk  = (((P + totalW - 1) / totalW) + 7) & ~7;   // 176
    int g0 = wid * chunk;
    int g1 = min(g0 + chunk, P);
    if (g0 >= g1) return;

    int g = g0;
    while (g < g1) {
        int b = g / Nc;
        int n = g - b * Nc;
        int nlimit = min(Nc, n + (g1 - g));     // batch-local end of our range

        // binary search: largest seg with offs[seg] <= n  (offs[0]=0)
        int seg = 0;
        #pragma unroll
        for (int step = 16; step; step >>= 1) {
            int cand = seg + step;
            if (cand <= Sc - 1 && __ldg(&offs[cand]) <= n) seg = cand;
        }

        while (n < nlimit) {
            int rend = min(nlimit, __ldg(&offs[seg + 1]));
            int key  = b * Sc + seg;

            float sA = 0.f, sB = 0.f, s2A = 0.f, s2B = 0.f;
            const float4* base = x4 + ((size_t)b * Nc + n) * C4;

            // 8-point groups: 192 consecutive float4s, 6 per lane.
            for (; n + 8 <= rend; n += 8, base += 192) {
                float4 v0 = __ldg(base + lane);
                float4 v1 = __ldg(base + lane + 32);
                float4 v2 = __ldg(base + lane + 64);
                float4 v3 = __ldg(base + lane + 96);
                float4 v4 = __ldg(base + lane + 128);
                float4 v5 = __ldg(base + lane + 160);
                sA += (v0.x + v0.y) + (v0.z + v0.w) + (v2.x + v2.y)
                    + (v2.z + v2.w) + (v4.x + v4.y) + (v4.z + v4.w);
                sB += (v1.x + v1.y) + (v1.z + v1.w) + (v3.x + v3.y)
                    + (v3.z + v3.w) + (v5.x + v5.y) + (v5.z + v5.w);
                s2A = fmaf(v0.x, v0.x, s2A); s2A = fmaf(v0.y, v0.y, s2A);
                s2A = fmaf(v0.z, v0.z, s2A); s2A = fmaf(v0.w, v0.w, s2A);
                s2B = fmaf(v1.x, v1.x, s2B); s2B = fmaf(v1.y, v1.y, s2B);
                s2B = fmaf(v1.z, v1.z, s2B); s2B = fmaf(v1.w, v1.w, s2B);
                s2A = fmaf(v2.x, v2.x, s2A); s2A = fmaf(v2.y, v2.y, s2A);
                s2A = fmaf(v2.z, v2.z, s2A); s2A = fmaf(v2.w, v2.w, s2A);
                s2B = fmaf(v3.x, v3.x, s2B); s2B = fmaf(v3.y, v3.y, s2B);
                s2B = fmaf(v3.z, v3.z, s2B); s2B = fmaf(v3.w, v3.w, s2B);
                s2A = fmaf(v4.x, v4.x, s2A); s2A = fmaf(v4.y, v4.y, s2A);
                s2A = fmaf(v4.z, v4.z, s2A); s2A = fmaf(v4.w, v4.w, s2A);
                s2B = fmaf(v5.x, v5.x, s2B); s2B = fmaf(v5.y, v5.y, s2B);
                s2B = fmaf(v5.z, v5.z, s2B); s2B = fmaf(v5.w, v5.w, s2B);
            }
            // remainder: single points, 24 active lanes
            for (; n < rend; ++n, base += 24) {
                if (lane < C4) {
                    float4 v = __ldg(base + lane);
                    sA += (v.x + v.y) + (v.z + v.w);
                    s2A = fmaf(v.x, v.x, s2A); s2A = fmaf(v.y, v.y, s2A);
                    s2A = fmaf(v.z, v.z, s2A); s2A = fmaf(v.w, v.w, s2A);
                }
            }

            // flush this run
            float s = sA + sB, s2 = s2A + s2B;
            #pragma unroll
            for (int o = 16; o; o >>= 1) {
                s  += __shfl_xor_sync(0xffffffffu, s,  o);
                s2 += __shfl_xor_sync(0xffffffffu, s2, o);
            }
            if (lane == 0) {
                atomicAdd(&g_sum[key],   s);
                atomicAdd(&g_sumsq[key], s2);
            }
            if (n < nlimit) ++seg;   // next segment in this batch
        }
        g = b * Nc + nlimit;         // next batch-slice re-searches seg
    }
}

// Per-(key, c4) scale/shift tables: o = x * sc + sh.
__global__ void pln_finalize_kernel(const int* __restrict__ offs,
                                    const float4* __restrict__ w4,
                                    const float4* __restrict__ b4)
{
    int i = blockIdx.x * blockDim.x + threadIdx.x;
    if (i < KEYS * C4) {
        int k  = i / C4;
        int c4 = i - k * C4;
        int seg = k & (Sc - 1);
        float cnt = (float)(offs[seg + 1] - offs[seg]) * (float)Cc;
        float m   = g_sum[k] / cnt;
        float var = g_sumsq[k] / cnt - m * m;
        float iv  = rsqrtf(var + EPSF);
        float4 wv = __ldg(w4 + c4);
        float4 bv = __ldg(b4 + c4);
        float4 sc, sh;
        sc.x = iv * wv.x; sh.x = fmaf(-m, sc.x, bv.x);
        sc.y = iv * wv.y; sh.y = fmaf(-m, sc.y, bv.y);
        sc.z = iv * wv.z; sh.z = fmaf(-m, sc.z, bv.z);
        sc.w = iv * wv.w; sh.w = fmaf(-m, sc.w, bv.w);
        g_sc[i] = sc;
        g_sh[i] = sh;
    }
}

// Norm: identical to R6 (measured 96us, at the LTS cap).
__global__ __launch_bounds__(256) void pln_norm_kernel(
    const float4* __restrict__ x4, const int* __restrict__ idx,
    float4* __restrict__ out4)
{
    const int P = Bc * Nc;
    const int E = P * C4;                      // 19,200,000 float4s
    int T   = gridDim.x * blockDim.x;          // multiple of 24 by launch config
    int tid = blockIdx.x * blockDim.x + threadIdx.x;
    int dp  = T / C4;

    int p  = tid / C4;
    int c4 = tid - p * C4;
    int b  = p / Nc;
    int n  = p - b * Nc;

    for (int e = tid; e < E; e += T) {
        int key = (b * Sc + __ldg(&idx[n])) & (KEYS - 1);
        int t   = key * C4 + c4;
        float4 sc = g_sc[t];
        float4 sh = g_sh[t];
        float4 xv = __ldcs(x4 + e);
        float4 o;
        o.x = fmaf(xv.x, sc.x, sh.x);
        o.y = fmaf(xv.y, sc.y, sh.y);
        o.z = fmaf(xv.z, sc.z, sh.z);
        o.w = fmaf(xv.w, sc.w, sh.w);
        __stcs(out4 + e, o);
        n += dp;
        if (n >= Nc) { n -= Nc; ++b; }
    }
}

extern "C" void kernel_launch(void* const* d_in, const int* in_sizes, int n_in,
                              void* d_out, int out_size) {
    const float4* x4   = (const float4*)d_in[0];
    const int*    offs = (const int*)d_in[1];
    const int*    idx  = (const int*)d_in[2];
    const float4* w4   = (const float4*)d_in[3];
    const float4* b4   = (const float4*)d_in[4];
    float4* out4 = (float4*)d_out;

    pln_zero_kernel<<<1, 128>>>();
    pln_reduce_kernel<<<RGRID, 256>>>(x4, offs);
    pln_finalize_kernel<<<12, 256>>>(offs, w4, b4);
    // grid*256 divisible by 24 -> grid divisible by 3.
    pln_norm_kernel<<<1185, 256>>>(x4, idx, out4);
}